// round 12
// baseline (speedup 1.0000x reference)
#include <cuda_runtime.h>
#include <cuda_bf16.h>
#include <cstdint>

static constexpr int BATCH = 8;
static constexpr int LQ    = 2048;
static constexpr int LKV   = 2048;
static constexpr int DIM   = 128;   // D == DV == 128
static constexpr float SM_SCALE = 0.08838834764831845f; // 1/sqrt(128)

// Scratch (device globals; no runtime allocation allowed)
__device__ __align__(128) float g_Qt[(size_t)BATCH * LQ  * DIM];   // tf32 bits
__device__ __align__(128) float g_Kt[(size_t)BATCH * LKV * DIM];   // tf32 bits
__device__ __align__(128) float g_Vt[(size_t)BATCH * DIM * LKV];   // V^T, tf32 bits
// per-row partial exp-sums: [B*LQ][32]  (16 n-tiles x 2 n-warps), deterministic
__device__ __align__(128) float g_partial[(size_t)BATCH * LQ * 32];

// ---------------------------------------------------------------------------
// Helpers
// ---------------------------------------------------------------------------
__device__ __forceinline__ uint32_t smem_u32(const void* p) {
    uint32_t a;
    asm("{ .reg .u64 t; cvta.to.shared.u64 t, %1; cvt.u32.u64 %0, t; }"
        : "=r"(a) : "l"(p));
    return a;
}
__device__ __forceinline__ float4 lds_f32x4(uint32_t a) {
    float4 v;
    asm volatile("ld.shared.v4.f32 {%0,%1,%2,%3}, [%4];"
                 : "=f"(v.x), "=f"(v.y), "=f"(v.z), "=f"(v.w) : "r"(a));
    return v;
}
__device__ __forceinline__ uint32_t f2tf(float f) {
    uint32_t r;
    asm("cvt.rna.tf32.f32 %0, %1;" : "=r"(r) : "f"(f));
    return r;
}
__device__ __forceinline__ uint32_t lds_u32(uint32_t a) { // raw tf32 bits
    uint32_t v;
    asm volatile("ld.shared.b32 %0, [%1];" : "=r"(v) : "r"(a));
    return v;
}
__device__ __forceinline__ void mma_tf32(float* d, const uint32_t* a, const uint32_t* b) {
    asm volatile("mma.sync.aligned.m16n8k8.row.col.f32.tf32.tf32.f32 "
                 "{%0,%1,%2,%3}, {%4,%5,%6,%7}, {%8,%9}, {%0,%1,%2,%3};"
                 : "+f"(d[0]), "+f"(d[1]), "+f"(d[2]), "+f"(d[3])
                 : "r"(a[0]), "r"(a[1]), "r"(a[2]), "r"(a[3]), "r"(b[0]), "r"(b[1]));
}
#define CP_ASYNC16(dst, src) \
    asm volatile("cp.async.cg.shared.global [%0], [%1], 16;" :: "r"(dst), "l"(src) : "memory")
#define CP_COMMIT()  asm volatile("cp.async.commit_group;" ::: "memory")
#define CP_WAIT(n)   asm volatile("cp.async.wait_group %0;" :: "n"(n) : "memory")

// ---------------------------------------------------------------------------
// Prep A: elementwise tf32 truncation of Q and K into scratch
// ---------------------------------------------------------------------------
__global__ __launch_bounds__(256) void qk_tf32_kernel(
    const float* __restrict__ Q, const float* __restrict__ K)
{
    const size_t t = (size_t)blockIdx.x * 256 + threadIdx.x;   // float4 index
    const bool isK = blockIdx.y != 0;
    const float4 v = ((const float4*)(isK ? K : Q))[t];
    uint4 o = make_uint4(f2tf(v.x), f2tf(v.y), f2tf(v.z), f2tf(v.w));
    ((uint4*)(isK ? g_Kt : g_Qt))[t] = o;
}

// ---------------------------------------------------------------------------
// Prep B: transpose V and pre-truncate to tf32:  V[b][k][n] -> g_Vt[b][n][k]
// ---------------------------------------------------------------------------
__global__ __launch_bounds__(256) void vt_tf32_kernel(const float* __restrict__ V)
{
    __shared__ float t[32][33];
    const int b  = blockIdx.z;
    const int k0 = blockIdx.y * 32;
    const int n0 = blockIdx.x * 32;
    const int tx = threadIdx.x & 31;
    const int ty = threadIdx.x >> 5;   // 0..7

    #pragma unroll
    for (int i = 0; i < 4; i++) {
        int k = ty + i * 8;
        t[k][tx] = V[((size_t)b * LKV + k0 + k) * DIM + n0 + tx];
    }
    __syncthreads();
    #pragma unroll
    for (int i = 0; i < 4; i++) {
        int n = ty + i * 8;
        uint32_t bits = f2tf(t[tx][n]);
        *(uint32_t*)&g_Vt[((size_t)b * DIM + n0 + n) * LKV + k0 + tx] = bits;
    }
}

// ---------------------------------------------------------------------------
// GEMM1: E = exp(scale * Q K^T), tf32 single-pass, operands pre-truncated.
// CTA tile 128x128, 8 warps (warp tile 32x64).  K=128 in 4 chunks of 32,
// 3-stage cp.async pipeline, padded-linear smem (row = 32 floats + 4 pad).
// Writes E (tf32-rounded fp32) into the weights region + per-row partials.
// (UNCHANGED from R11 — it was the win there.)
// ---------------------------------------------------------------------------
static constexpr int G1_ROWB  = 144;              // bytes per smem row
static constexpr int G1_TILE  = 128 * G1_ROWB;    // 18432 per operand
static constexpr int G1_STAGE = 2 * G1_TILE;      // Q + K = 36864
static constexpr int G1_SMEM  = 1024 + 3 * G1_STAGE;   // 111616

__global__ __launch_bounds__(256, 2) void gemm1_mma_kernel(float* __restrict__ S)
{
    extern __shared__ char smem[];
    const uint32_t sb = (smem_u32(smem) + 1023u) & ~1023u;

    const int tid  = threadIdx.x;
    const int lane = tid & 31;
    const int w    = tid >> 5;
    const int wm   = (w >> 1) * 32;   // 4 warps in M
    const int wn   = (w & 1) * 64;    // 2 warps in N

    const int b  = blockIdx.z;
    const int m0 = blockIdx.y * 128;
    const int n0 = blockIdx.x * 128;

    const float* Qb = g_Qt + ((size_t)b * LQ  + m0) * DIM;
    const float* Kb = g_Kt + ((size_t)b * LKV + n0) * DIM;
    float*       Sb = S + (size_t)b * LQ * LKV;

    auto load_chunk = [&](int c, int stage) {
        const int k0 = c * 32;
        const uint32_t base = sb + (uint32_t)stage * G1_STAGE;
        #pragma unroll
        for (int i = 0; i < 4; i++) {
            int u = i * 256 + tid;          // 0..1023
            int row = u >> 3, un = (u & 7) * 16;
            uint32_t off = (uint32_t)row * G1_ROWB + un;
            CP_ASYNC16(base + off,           Qb + (size_t)row * DIM + k0 + (un >> 2));
            CP_ASYNC16(base + G1_TILE + off, Kb + (size_t)row * DIM + k0 + (un >> 2));
        }
    };

    float acc[2][8][4] = {};

    const uint32_t g = lane >> 2;     // 0..7
    const uint32_t cc4 = (lane & 3);  // 0..3

    load_chunk(0, 0); CP_COMMIT();
    load_chunk(1, 1); CP_COMMIT();

    for (int c = 0; c < 4; c++) {
        if (c < 3) { CP_WAIT(1); } else { CP_WAIT(0); }
        __syncthreads();   // chunk c resident; all warps past chunk c-1

        if (c < 2) { load_chunk(c + 2, (c + 2) % 3); CP_COMMIT(); }

        const uint32_t base = sb + (uint32_t)(c % 3) * G1_STAGE;
        const uint32_t QS = base, KS = base + G1_TILE;

        #pragma unroll
        for (int ks = 0; ks < 4; ks++) {
            const uint32_t kb = ks * 8;   // k offset in floats
            uint32_t A[2][4], B[8][2];

            #pragma unroll
            for (int mf = 0; mf < 2; mf++) {
                uint32_t a0 = QS + (uint32_t)(wm + mf * 16 + g) * G1_ROWB + (kb + cc4) * 4;
                A[mf][0] = lds_u32(a0);
                A[mf][1] = lds_u32(a0 + 8 * G1_ROWB);
                A[mf][2] = lds_u32(a0 + 16);
                A[mf][3] = lds_u32(a0 + 8 * G1_ROWB + 16);
            }
            #pragma unroll
            for (int nf = 0; nf < 8; nf++) {
                uint32_t b0 = KS + (uint32_t)(wn + nf * 8 + g) * G1_ROWB + (kb + cc4) * 4;
                B[nf][0] = lds_u32(b0);
                B[nf][1] = lds_u32(b0 + 16);
            }
            #pragma unroll
            for (int mf = 0; mf < 2; mf++)
                #pragma unroll
                for (int nf = 0; nf < 8; nf++)
                    mma_tf32(acc[mf][nf], A[mf], B[nf]);
        }
    }

    // epilogue: scale, exp, round to tf32 (so gemm2 needs no cvt), store;
    // per-row partial sums over the ROUNDED values (consistent normalization)
    const int er = lane >> 2;
    const int ec = (lane & 3) * 2;
    float rsum[2][2] = {{0.f, 0.f}, {0.f, 0.f}};
    #pragma unroll
    for (int mf = 0; mf < 2; mf++)
        #pragma unroll
        for (int nf = 0; nf < 8; nf++) {
            float e0 = __uint_as_float(f2tf(__expf(fminf(acc[mf][nf][0] * SM_SCALE, 80.f))));
            float e1 = __uint_as_float(f2tf(__expf(fminf(acc[mf][nf][1] * SM_SCALE, 80.f))));
            float e2 = __uint_as_float(f2tf(__expf(fminf(acc[mf][nf][2] * SM_SCALE, 80.f))));
            float e3 = __uint_as_float(f2tf(__expf(fminf(acc[mf][nf][3] * SM_SCALE, 80.f))));
            int r = m0 + wm + mf * 16 + er;
            int nn = n0 + wn + nf * 8 + ec;
            *(float2*)(Sb + (size_t)r * LKV + nn)       = make_float2(e0, e1);
            *(float2*)(Sb + (size_t)(r + 8) * LKV + nn) = make_float2(e2, e3);
            rsum[mf][0] += e0 + e1;
            rsum[mf][1] += e2 + e3;
        }
    #pragma unroll
    for (int mf = 0; mf < 2; mf++)
        #pragma unroll
        for (int h = 0; h < 2; h++) {
            float v = rsum[mf][h];
            v += __shfl_xor_sync(0xffffffffu, v, 1);
            v += __shfl_xor_sync(0xffffffffu, v, 2);
            if ((lane & 3) == 0) {
                int row = m0 + wm + mf * 16 + h * 8 + er;
                g_partial[((size_t)b * LQ + row) * 32 + blockIdx.x * 2 + (w & 1)] = v;
            }
        }
}

// ---------------------------------------------------------------------------
// GEMM2: C = diag(inv) * (E V); W = E*inv in place over E (final fp32
// weights).  CTA tile 64(M) x 128(N=DV), K=2048 in 32 chunks of 64,
// 2-stage cp.async pipeline (R10 geometry — fatter chunks, fewer barriers),
// raw-bits loads (E tf32-rounded at source; V pre-truncated) — zero CVT in
// the hot loop.  One barrier per chunk; prefetch-after-sync is race-free.
// ---------------------------------------------------------------------------
static constexpr int G2_ROWB  = 272;               // 64 floats + 4 pad
static constexpr int G2_ETILE = 64 * G2_ROWB;      // 17408
static constexpr int G2_VTILE = 128 * G2_ROWB;     // 34816
static constexpr int G2_STAGE = G2_ETILE + G2_VTILE;    // 52224
static constexpr int G2_SMEM  = 1024 + 2 * G2_STAGE + 256;   // 105728

__global__ __launch_bounds__(256, 2) void gemm2_mma_kernel(
    float* __restrict__ W, float* __restrict__ C)
{
    extern __shared__ char smem[];
    const uint32_t sb = (smem_u32(smem) + 1023u) & ~1023u;
    float* inv_s = (float*)(smem + (sb - smem_u32(smem)) + 2 * G2_STAGE);

    const int tid  = threadIdx.x;
    const int lane = tid & 31;
    const int w    = tid >> 5;
    const int wm   = (w >> 2) * 32;   // 2 warps in M
    const int wn   = (w & 3) * 32;    // 4 warps in N

    const int m0 = blockIdx.x * 64;
    const int b  = blockIdx.y;

    float* Wb = W + ((size_t)b * LQ + m0) * LKV;          // E in, W out
    const float* Vt = g_Vt + (size_t)b * DIM * LKV;
    float* Cb = C + (size_t)b * LQ * DIM;

    // row inverse sums (deterministic reduction of 32 partials)
    if (tid < 64) {
        const float* p = g_partial + ((size_t)b * LQ + m0 + tid) * 32;
        float s = 0.f;
        #pragma unroll
        for (int j = 0; j < 32; j++) s += p[j];
        inv_s[tid] = 1.0f / s;
    }

    auto load_chunk = [&](int c, int stage) {
        const int k0 = c * 64;
        const uint32_t base = sb + (uint32_t)stage * G2_STAGE;
        #pragma unroll
        for (int i = 0; i < 4; i++) {       // E: 64 rows x 16 16B-units
            int u = i * 256 + tid;
            int row = u >> 4, un = (u & 15) * 16;
            uint32_t off = (uint32_t)row * G2_ROWB + un;
            CP_ASYNC16(base + off, Wb + (size_t)row * LKV + k0 + (un >> 2));
        }
        #pragma unroll
        for (int i = 0; i < 8; i++) {       // V: 128 rows x 16 16B-units
            int u = i * 256 + tid;
            int row = u >> 4, un = (u & 15) * 16;
            uint32_t off = (uint32_t)row * G2_ROWB + un;
            CP_ASYNC16(base + G2_ETILE + off, Vt + (size_t)row * LKV + k0 + (un >> 2));
        }
    };

    float acc[2][4][4] = {};

    const uint32_t g = lane >> 2;
    const uint32_t cc4 = (lane & 3);

    load_chunk(0, 0);
    CP_COMMIT();

    for (int c = 0; c < 32; c++) {
        CP_WAIT(0);
        __syncthreads();   // chunk c resident; all warps past chunk c-1

        if (c < 31) { load_chunk(c + 1, (c + 1) & 1); CP_COMMIT(); }

        const int k0 = c * 64;
        const uint32_t base = sb + (uint32_t)(c & 1) * G2_STAGE;
        const uint32_t ES = base, VS = base + G2_ETILE;

        // W = E * inv  -> final fp32 weights (STGs drain during MMA below)
        #pragma unroll
        for (int i = 0; i < 4; i++) {
            int u = i * 256 + tid;
            int row = u >> 4, un = (u & 15) * 16;
            float4 e = lds_f32x4(ES + (uint32_t)row * G2_ROWB + un);
            float inv = inv_s[row];
            *(float4*)(Wb + (size_t)row * LKV + k0 + (un >> 2)) =
                make_float4(e.x * inv, e.y * inv, e.z * inv, e.w * inv);
        }

        #pragma unroll
        for (int ks = 0; ks < 8; ks++) {
            const uint32_t kb = ks * 8;
            uint32_t A[2][4], B[4][2];

            #pragma unroll
            for (int mf = 0; mf < 2; mf++) {
                uint32_t a0 = ES + (uint32_t)(wm + mf * 16 + g) * G2_ROWB + (kb + cc4) * 4;
                A[mf][0] = lds_u32(a0);
                A[mf][1] = lds_u32(a0 + 8 * G2_ROWB);
                A[mf][2] = lds_u32(a0 + 16);
                A[mf][3] = lds_u32(a0 + 8 * G2_ROWB + 16);
            }
            #pragma unroll
            for (int nf = 0; nf < 4; nf++) {
                uint32_t b0 = VS + (uint32_t)(wn + nf * 8 + g) * G2_ROWB + (kb + cc4) * 4;
                B[nf][0] = lds_u32(b0);
                B[nf][1] = lds_u32(b0 + 16);
            }
            #pragma unroll
            for (int mf = 0; mf < 2; mf++)
                #pragma unroll
                for (int nf = 0; nf < 4; nf++)
                    mma_tf32(acc[mf][nf], A[mf], B[nf]);
        }
    }

    // epilogue: scale by row inverse sums, write context
    const int er = lane >> 2;
    const int ec = (lane & 3) * 2;
    #pragma unroll
    for (int mf = 0; mf < 2; mf++) {
        float i0 = inv_s[wm + mf * 16 + er];
        float i1 = inv_s[wm + mf * 16 + er + 8];
        #pragma unroll
        for (int nf = 0; nf < 4; nf++) {
            int r = m0 + wm + mf * 16 + er;
            int nn = wn + nf * 8 + ec;
            *(float2*)(Cb + (size_t)r * DIM + nn) =
                make_float2(acc[mf][nf][0] * i0, acc[mf][nf][1] * i0);
            *(float2*)(Cb + (size_t)(r + 8) * DIM + nn) =
                make_float2(acc[mf][nf][2] * i1, acc[mf][nf][3] * i1);
        }
    }
}

// ---------------------------------------------------------------------------
extern "C" void kernel_launch(void* const* d_in, const int* in_sizes, int n_in,
                              void* d_out, int out_size)
{
    const float* Q = (const float*)d_in[0];
    const float* K = (const float*)d_in[1];
    const float* V = (const float*)d_in[2];

    float* Wout = (float*)d_out;                            // (B,LQ,LKV)
    float* Cout = Wout + (size_t)BATCH * LQ * LKV;          // (B,LQ,DV)

    static bool attr_done = false;
    if (!attr_done) {
        cudaFuncSetAttribute(gemm1_mma_kernel,
            cudaFuncAttributeMaxDynamicSharedMemorySize, G1_SMEM);
        cudaFuncSetAttribute(gemm2_mma_kernel,
            cudaFuncAttributeMaxDynamicSharedMemorySize, G2_SMEM);
        attr_done = true;
    }

    dim3 gq((unsigned)((size_t)BATCH * LQ * DIM / 4 / 256), 2);
    qk_tf32_kernel<<<gq, 256>>>(Q, K);

    dim3 gt(DIM / 32, LKV / 32, BATCH);
    vt_tf32_kernel<<<gt, 256>>>(V);

    dim3 g1(LKV / 128, LQ / 128, BATCH);    // 16 x 16 x 8 = 2048 CTAs
    gemm1_mma_kernel<<<g1, 256, G1_SMEM>>>(Wout);

    dim3 g2(LQ / 64, BATCH);                // 32 x 8 = 256 CTAs
    gemm2_mma_kernel<<<g2, 256, G2_SMEM>>>(Wout, Cout);
}